// round 16
// baseline (speedup 1.0000x reference)
#include <cuda_runtime.h>
#include <cuda_bf16.h>
#include <cstdint>

// Problem dims
#define Tt 128
#define Bb 32
#define Ii 256
#define Hh 1024
#define Oo 128
#define BH (Bb*Hh)      // 32768 floats per timestep of h
#define MROWS (Tt*Bb)   // 4096 flattened (t,b) rows

// Scratch (device globals: no allocations allowed)
__device__ float g_xin[Tt*BH];        // X @ W_in^T, [T,B,H]
__device__ float g_h[(Tt+1)*BH];      // h_all[0..T], [T+1,B,H]
__device__ float g_err[MROWS*Oo];     // err, [T*B,O]
__device__ float g_c[MROWS*Hh];       // c, then (in-place) a, [T*B,H]
__device__ unsigned g_flags[128];     // [grp*32 + slice] progress flags (128B/grp)

// ---------------------------------------------------------------------------
// Packed fp32x2 FMA (Blackwell FFMA2: 2 fp32 FMAs per instruction)
// ---------------------------------------------------------------------------
__device__ __forceinline__ unsigned long long ffma2_(unsigned long long a,
                                                     unsigned long long b,
                                                     unsigned long long c)
{
    unsigned long long d;
    asm("fma.rn.f32x2 %0, %1, %2, %3;" : "=l"(d) : "l"(a), "l"(b), "l"(c));
    return d;
}
__device__ __forceinline__ unsigned long long dup2_(float x)
{
    unsigned long long d;
    asm("mov.b64 %0, {%1, %1};" : "=l"(d) : "f"(x));
    return d;
}
union F4U { float4 f; unsigned long long u[2]; float s[4]; };
union U2F { unsigned long long u; float2 f; };

// ---------------------------------------------------------------------------
// cp.async helper (LDGSTS .cg: bypasses L1 -> coherent with other SMs' stores)
// ---------------------------------------------------------------------------
__device__ __forceinline__ void cp16(uint32_t saddr, const void* gptr)
{
    asm volatile("cp.async.cg.shared.global [%0], [%1], 16;\n" :: "r"(saddr), "l"(gptr));
}

// ---------------------------------------------------------------------------
// setup_kernel: zero ys + split-K targets, reset flags, copy h0 -> g_h[0]
// err_kernel:  err = ys - target (elementwise, after split-K O GEMM)
// ---------------------------------------------------------------------------
__global__ void setup_kernel(float* __restrict__ ys, int nys,
                             float* __restrict__ gw, int ngw,
                             const float* __restrict__ h0)
{
    int i = blockIdx.x * blockDim.x + threadIdx.x;
    if (i < 128) g_flags[i] = 0u;
    if (i < BH) g_h[i] = h0[i];
    for (int k = i; k < nys; k += gridDim.x * blockDim.x) ys[k] = 0.f;
    for (int k = i; k < ngw; k += gridDim.x * blockDim.x) gw[k] = 0.f;
}

__global__ void err_kernel(const float* __restrict__ ys,
                           const float* __restrict__ target)
{
    int i = blockIdx.x * blockDim.x + threadIdx.x;
    if (i < MROWS * Oo) g_err[i] = ys[i] - target[i];
}

// ---------------------------------------------------------------------------
// Forward scan: h_{t+1} = tanh(xin_t + h_t @ W_hh^T)
// (Engine frozen at best-measured config: 4 groups x 32 slices, 256 thr;
//  W_hh in registers, warp w (0..7) = k-slice [128w,128w+128), lane = row.)
// R16: lane-parallel flag barrier. Each CTA publishes ONE st.release flag;
// warp 0's 32 lanes poll the group's 32 flags with one coalesced 128B
// ld.acquire per iteration (__any_sync exit). No serialized atomic chain.
// ---------------------------------------------------------------------------
__global__ void __launch_bounds__(256, 1) scan_fwd(const float* __restrict__ Whh,
                                                   float* __restrict__ hf_out)
{
    __shared__ float hs[8 * Hh];          // 32KB staged h for this group's batches
    __shared__ float part[8 * 8 * 32];    // 8KB partials [kslice][b][j]

    int tid = threadIdx.x;
    int grp = blockIdx.x >> 5;            // batch group 0..3
    int sl  = blockIdx.x & 31;            // row slice 0..31
    int jbase = sl * 32;
    int bbase = grp * 8;

    int w  = tid >> 5;                    // k-slice == warp id (0..7)
    int jl = tid & 31;                    // row within slice (lane)
    int kbase = w * 128;

    // One-time: W[jbase+jl][kbase .. kbase+128) into 64 f32x2 registers
    unsigned long long wreg[64];
    {
        const float* wr = Whh + (size_t)(jbase + jl) * Hh + kbase;
        #pragma unroll
        for (int i = 0; i < 32; ++i) {
            F4U v; v.f = *(const float4*)&wr[i * 4];
            wreg[2 * i] = v.u[0]; wreg[2 * i + 1] = v.u[1];
        }
    }

    int eb = tid >> 5;                    // epilogue batch (0..7)
    int ej = tid & 31;                    // epilogue row within slice
    uint32_t hs_base = (uint32_t)__cvta_generic_to_shared(hs);
    unsigned* myflag        = &g_flags[grp * 32 + sl];
    const unsigned* laneflg = &g_flags[grp * 32 + jl];   // warp-0 lane polls this

    for (int t = 0; t < Tt; ++t) {
        const float* hcur = g_h + (size_t)t * BH + (size_t)bbase * Hh;

        // Stage 8*1024 floats = 2048 float4 over 256 threads; 2 commit groups
        #pragma unroll
        for (int r = 0; r < 4; ++r) {
            int f = tid + (r << 8);
            cp16(hs_base + (f << 4), hcur + (f << 2));
        }
        asm volatile("cp.async.commit_group;\n");
        #pragma unroll
        for (int r = 4; r < 8; ++r) {
            int f = tid + (r << 8);
            cp16(hs_base + (f << 4), hcur + (f << 2));
        }
        asm volatile("cp.async.commit_group;\n");

        float accx = g_xin[(size_t)t * BH + (size_t)(bbase + eb) * Hh + jbase + ej];

        unsigned long long acc0[8], acc1[8];   // 2 chains per batch
        #pragma unroll
        for (int b = 0; b < 8; ++b) { acc0[b] = 0ull; acc1[b] = 0ull; }

        asm volatile("cp.async.wait_group 1;\n" ::: "memory");
        __syncthreads();
        #pragma unroll
        for (int b = 0; b < 4; ++b) {
            const float* hb = hs + b * Hh + kbase;
            #pragma unroll
            for (int i = 0; i < 32; ++i) {
                F4U hv; hv.f = *(const float4*)&hb[i * 4];   // warp-broadcast
                acc0[b] = ffma2_(hv.u[0], wreg[2 * i],     acc0[b]);
                acc1[b] = ffma2_(hv.u[1], wreg[2 * i + 1], acc1[b]);
            }
        }
        asm volatile("cp.async.wait_group 0;\n" ::: "memory");
        __syncthreads();
        #pragma unroll
        for (int b = 4; b < 8; ++b) {
            const float* hb = hs + b * Hh + kbase;
            #pragma unroll
            for (int i = 0; i < 32; ++i) {
                F4U hv; hv.f = *(const float4*)&hb[i * 4];
                acc0[b] = ffma2_(hv.u[0], wreg[2 * i],     acc0[b]);
                acc1[b] = ffma2_(hv.u[1], wreg[2 * i + 1], acc1[b]);
            }
        }

        // k-slice partials -> SMEM
        #pragma unroll
        for (int b = 0; b < 8; ++b) {
            U2F a, c; a.u = acc0[b]; c.u = acc1[b];
            part[w * 256 + b * 32 + jl] = (a.f.x + a.f.y) + (c.f.x + c.f.y);
        }
        __syncthreads();

        // Reduce 8 slices; thread (eb, ej)
        float s = accx;
        #pragma unroll
        for (int ww = 0; ww < 8; ++ww) s += part[ww * 256 + eb * 32 + ej];
        float hn = tanhf(s);
        __stcg(&g_h[(size_t)(t + 1) * BH + (size_t)(bbase + eb) * Hh + jbase + ej], hn);

        if (t == Tt - 1) {
            hf_out[(bbase + eb) * Hh + jbase + ej] = hn;
            break;
        }

        // Lane-parallel flag barrier (32 CTAs):
        // stores -> bar.sync -> ONE release-store -> 32-lane acquire-poll.
        __syncthreads();
        if (tid < 32) {
            unsigned tgt = (unsigned)(t + 1);
            if (tid == 0)
                asm volatile("st.release.gpu.u32 [%0], %1;"
                             :: "l"(myflag), "r"(tgt) : "memory");
            unsigned v;
            do {
                asm volatile("ld.acquire.gpu.u32 %0, [%1];"
                             : "=r"(v) : "l"(laneflg) : "memory");
            } while (__any_sync(0xFFFFFFFFu, v < tgt));
        }
        __syncthreads();
    }
}

// ---------------------------------------------------------------------------
// Backward scan (elementwise, parallel over (b,j)):
//   a_t = c_t + diag(W_hh)[j] * (1 - h_all[t+1]^2) * a_{t+1}, in place in g_c
// ---------------------------------------------------------------------------
__global__ void scan_bwd(const float* __restrict__ Whh)
{
    int flat = blockIdx.x * blockDim.x + threadIdx.x;  // 0..BH-1
    int j = flat & (Hh - 1);
    float dw = Whh[(size_t)j * Hh + j];
    float a = g_c[(size_t)(Tt - 1) * BH + flat];
    for (int t = Tt - 2; t >= 0; --t) {
        float h   = g_h[(size_t)(t + 1) * BH + flat];
        float php = 1.f - h * h;
        a = g_c[(size_t)t * BH + flat] + dw * php * a;
        g_c[(size_t)t * BH + flat] = a;
    }
}

// ---------------------------------------------------------------------------
// Tiled fp32 GEMM, double-buffered, fp32x2 inner (engine frozen).
// R16: __launch_bounds__(256, 2) -> cap regs at 128 so 2 CTAs co-reside per
// SM (25.6KB smem x2 fits), doubling latency-hiding warps.
// Tile TM x 64, 256 threads, (TM/16) x 4 micro-tile.
// SPLITK via blockIdx.z (chunk length Kc) + ATOMIC epilogue into zeroed out.
// EPI: 0 plain store; 1 store + err=acc-Q0 into P1; 2 store acc*(1-Q0^2).
// ---------------------------------------------------------------------------
template<int TM, bool AKC, bool BKC, int EPI, bool ATOMIC>
__global__ void __launch_bounds__(256, 2) gemmT(const float* __restrict__ A, int sAm, int sAk,
                                                const float* __restrict__ B, int sBn, int sBk,
                                                int N, int Kc, float scale,
                                                float* __restrict__ P0, float* __restrict__ P1,
                                                const float* __restrict__ Q0)
{
    constexpr int MI  = TM / 16;     // per-thread m extent (4 or 8)
    constexpr int NLA = TM / 64;     // A-loader iterations (1 or 2)
    __shared__ float As[2][16][TM + 4];
    __shared__ float Bs[2][16][68];
    int tid = threadIdx.x;
    int m0 = blockIdx.y * TM, n0 = blockIdx.x * 64;
    int kbeg = blockIdx.z * Kc, kend = kbeg + Kc;
    int ty = tid >> 4, tx = tid & 15;

    float4 aP[NLA], bP;
    auto loadA = [&](int k0) {
        #pragma unroll
        for (int it = 0; it < NLA; ++it) {
            int f = tid + (it << 8);
            if (AKC) { int r = f >> 2, kk = (f & 3) << 2;
                aP[it] = *(const float4*)&A[(size_t)(m0 + r) * sAm + k0 + kk]; }
            else { int kk = f / (TM / 4), r = (f % (TM / 4)) << 2;
                aP[it] = *(const float4*)&A[(size_t)(k0 + kk) * sAk + m0 + r]; }
        }
    };
    auto storeA = [&](int p) {
        #pragma unroll
        for (int it = 0; it < NLA; ++it) {
            int f = tid + (it << 8);
            if (AKC) { int r = f >> 2, kk = (f & 3) << 2;
                As[p][kk][r] = aP[it].x; As[p][kk+1][r] = aP[it].y;
                As[p][kk+2][r] = aP[it].z; As[p][kk+3][r] = aP[it].w; }
            else { int kk = f / (TM / 4), r = (f % (TM / 4)) << 2;
                *(float4*)&As[p][kk][r] = aP[it]; }
        }
    };
    auto loadB = [&](int k0) {
        if (BKC) { int r = tid >> 2, kk = (tid & 3) << 2;
            bP = *(const float4*)&B[(size_t)(n0 + r) * sBn + k0 + kk]; }
        else { int kk = tid >> 4, r = (tid & 15) << 2;
            bP = *(const float4*)&B[(size_t)(k0 + kk) * sBk + n0 + r]; }
    };
    auto storeB = [&](int p) {
        if (BKC) { int r = tid >> 2, kk = (tid & 3) << 2;
            Bs[p][kk][r] = bP.x; Bs[p][kk+1][r] = bP.y;
            Bs[p][kk+2][r] = bP.z; Bs[p][kk+3][r] = bP.w; }
        else { int kk = tid >> 4, r = (tid & 15) << 2;
            *(float4*)&Bs[p][kk][r] = bP; }
    };

    loadA(kbeg); loadB(kbeg);
    storeA(0);   storeB(0);
    __syncthreads();

    unsigned long long acc2[MI / 2][4];
    #pragma unroll
    for (int i = 0; i < MI / 2; ++i)
        #pragma unroll
        for (int j = 0; j < 4; ++j) acc2[i][j] = 0ull;

    int p = 0;
    for (int k0 = kbeg; k0 < kend; k0 += 16) {
        bool more = (k0 + 16) < kend;
        if (more) { loadA(k0 + 16); loadB(k0 + 16); }
        #pragma unroll
        for (int kk = 0; kk < 16; ++kk) {
            F4U bv; bv.f = *(float4*)&Bs[p][kk][tx << 2];
            unsigned long long d0 = dup2_(bv.s[0]), d1 = dup2_(bv.s[1]);
            unsigned long long d2 = dup2_(bv.s[2]), d3 = dup2_(bv.s[3]);
            #pragma unroll
            for (int q = 0; q < MI / 4; ++q) {
                F4U av; av.f = *(float4*)&As[p][kk][ty * MI + q * 4];
                acc2[2*q  ][0] = ffma2_(av.u[0], d0, acc2[2*q  ][0]);
                acc2[2*q+1][0] = ffma2_(av.u[1], d0, acc2[2*q+1][0]);
                acc2[2*q  ][1] = ffma2_(av.u[0], d1, acc2[2*q  ][1]);
                acc2[2*q+1][1] = ffma2_(av.u[1], d1, acc2[2*q+1][1]);
                acc2[2*q  ][2] = ffma2_(av.u[0], d2, acc2[2*q  ][2]);
                acc2[2*q+1][2] = ffma2_(av.u[1], d2, acc2[2*q+1][2]);
                acc2[2*q  ][3] = ffma2_(av.u[0], d3, acc2[2*q  ][3]);
                acc2[2*q+1][3] = ffma2_(av.u[1], d3, acc2[2*q+1][3]);
            }
        }
        if (more) { storeA(p ^ 1); storeB(p ^ 1); __syncthreads(); p ^= 1; }
    }

    // acc2[pr] holds m-offsets (2pr, 2pr+1) relative to ty*MI (pairs from the
    // float4 halves); epilogue enumerates m = m0 + ty*MI + pr*2 + h2.
    #pragma unroll
    for (int pr = 0; pr < MI / 2; ++pr) {
        #pragma unroll
        for (int h2 = 0; h2 < 2; ++h2) {
            int m = m0 + ty * MI + pr * 2 + h2;
            #pragma unroll
            for (int jx = 0; jx < 4; ++jx) {
                int n = n0 + (tx << 2) + jx;
                U2F uv; uv.u = acc2[pr][jx];
                float v = (h2 ? uv.f.y : uv.f.x) * scale;
                size_t idx = (size_t)m * N + n;
                if (ATOMIC) {
                    atomicAdd(&P0[idx], v);
                } else if (EPI == 0) {
                    P0[idx] = v;
                } else if (EPI == 1) {          // O -> ys, err = O - target
                    P0[idx] = v;
                    P1[idx] = v - Q0[idx];
                } else {                        // c = L * (1 - hnew^2)
                    float h = Q0[idx];
                    P0[idx] = v * (1.f - h * h);
                }
            }
        }
    }
}

// ---------------------------------------------------------------------------
// Launch sequence (graph-capturable: kernel launches only)
// ---------------------------------------------------------------------------
extern "C" void kernel_launch(void* const* d_in, const int* in_sizes, int n_in,
                              void* d_out, int out_size)
{
    const float* x      = (const float*)d_in[0];  // [T,B,I]
    const float* target = (const float*)d_in[1];  // [T,B,O]
    const float* h0     = (const float*)d_in[2];  // [B,H]
    const float* W_in   = (const float*)d_in[3];  // [H,I]
    const float* W_hh   = (const float*)d_in[4];  // [H,H]
    const float* W_out  = (const float*)d_in[5];  // [O,H]

    float* out   = (float*)d_out;
    float* ys    = out;                                   // [T*B, O]
    float* hf    = out + (size_t)MROWS * Oo;              // [B,H]
    float* gwout = hf + BH;                               // [O,H]
    float* gwih  = gwout + (size_t)Oo * Hh;               // [H,I]
    float* gwhh  = gwih + (size_t)Hh * Ii;                // [H,H]

    float *p_xin, *p_h, *p_err, *p_c;
    cudaGetSymbolAddress((void**)&p_xin, g_xin);
    cudaGetSymbolAddress((void**)&p_h,   g_h);
    cudaGetSymbolAddress((void**)&p_err, g_err);
    cudaGetSymbolAddress((void**)&p_c,   g_c);

    // 0. zero ys + split-K targets + flags + h_all[0] (one kernel)
    // (kNumZero, NOT "NZERO": glibc <limits.h> defines NZERO=20 on the GPU host)
    const int kNumZero = Oo * Hh + Hh * Ii + Hh * Hh;   // gwout..gwhh contiguous
    setup_kernel<<<256, 256>>>(ys, MROWS * Oo, gwout, kNumZero, h0);

    // 1. Xin = X @ W_in^T            [4096,1024], K=256  (DOT)
    gemmT<128, true, true, 0, false><<<dim3(Hh / 64, MROWS / 128, 1), 256>>>(
        x, Ii, 1, W_in, Ii, 1, Hh, Ii, 1.f, p_xin, nullptr, nullptr);

    // 2. forward scan (persistent, 4 batch-groups x 32 slices, 256 thr)
    scan_fwd<<<128, 256>>>(W_hh, hf);

    // 3. O = Hnew @ W_out^T -> ys    [4096,128], K=1024, split 4 -> 512 CTAs
    gemmT<64, true, true, 0, true><<<dim3(Oo / 64, MROWS / 64, 4), 256>>>(
        p_h + BH, Hh, 1, W_out, Hh, 1, Oo, Hh / 4, 1.f, ys, nullptr, nullptr);

    // 4. err = ys - target (elementwise)
    err_kernel<<<(MROWS * Oo) / 256, 256>>>(ys, target);

    // 5. c = (err @ W_out) * (1 - hnew^2)                [4096,1024], K=128 (NN)
    gemmT<128, true, false, 2, false><<<dim3(Hh / 64, MROWS / 128, 1), 256>>>(
        p_err, Oo, 1, W_out, 1, Hh, Hh, Oo, 1.f, p_c, nullptr, p_h + BH);

    // 6. backward scan: c -> a (in place)
    scan_bwd<<<BH / 256, 256>>>(W_hh);

    // 7. g_wout = (1/B) * err^T @ Hnew       [128,1024], K=4096, split 16 -> 256 CTAs
    gemmT<128, false, false, 0, true><<<dim3(Hh / 64, Oo / 128, 16), 256>>>(
        p_err, 1, Oo, p_h + BH, 1, Hh, Hh, MROWS / 16, 1.f / Bb, gwout, nullptr, nullptr);

    // 8. g_wih = (1e-3/B) * a^T @ X          [1024,256], K=4096, split 8 -> 256 CTAs
    gemmT<128, false, false, 0, true><<<dim3(Ii / 64, Hh / 128, 8), 256>>>(
        p_c, 1, Hh, x, 1, Ii, Ii, MROWS / 8, 1e-3f / Bb, gwih, nullptr, nullptr);

    // 9. g_whh = (1e-5/B) * a^T @ Hprev      [1024,1024], K=4096, split 4 -> 512 CTAs
    gemmT<128, false, false, 0, true><<<dim3(Hh / 64, Hh / 128, 4), 256>>>(
        p_c, 1, Hh, p_h, 1, Hh, Hh, MROWS / 4, 1e-5f / Bb, gwhh, nullptr, nullptr);
}

// round 17
// speedup vs baseline: 1.5292x; 1.5292x over previous
#include <cuda_runtime.h>
#include <cuda_bf16.h>
#include <cstdint>

// Problem dims
#define Tt 128
#define Bb 32
#define Ii 256
#define Hh 1024
#define Oo 128
#define BH (Bb*Hh)      // 32768 floats per timestep of h
#define MROWS (Tt*Bb)   // 4096 flattened (t,b) rows

// Scratch (device globals: no allocations allowed)
__device__ float g_xin[Tt*BH];        // X @ W_in^T, [T,B,H]
__device__ float g_h[(Tt+1)*BH];      // h_all[0..T], [T+1,B,H]
__device__ float g_err[MROWS*Oo];     // err, [T*B,O]
__device__ float g_c[MROWS*Hh];       // c, then (in-place) a, [T*B,H]
__device__ unsigned g_bars[128];      // 4 group barriers, stride 32 (separate lines)

// ---------------------------------------------------------------------------
// Packed fp32x2 FMA (Blackwell FFMA2: 2 fp32 FMAs per instruction)
// ---------------------------------------------------------------------------
__device__ __forceinline__ unsigned long long ffma2_(unsigned long long a,
                                                     unsigned long long b,
                                                     unsigned long long c)
{
    unsigned long long d;
    asm("fma.rn.f32x2 %0, %1, %2, %3;" : "=l"(d) : "l"(a), "l"(b), "l"(c));
    return d;
}
__device__ __forceinline__ unsigned long long dup2_(float x)
{
    unsigned long long d;
    asm("mov.b64 %0, {%1, %1};" : "=l"(d) : "f"(x));
    return d;
}
union F4U { float4 f; unsigned long long u[2]; float s[4]; };
union U2F { unsigned long long u; float2 f; };

// ---------------------------------------------------------------------------
// cp.async helper (LDGSTS .cg: bypasses L1 -> coherent with other SMs' stores)
// ---------------------------------------------------------------------------
__device__ __forceinline__ void cp16(uint32_t saddr, const void* gptr)
{
    asm volatile("cp.async.cg.shared.global [%0], [%1], 16;\n" :: "r"(saddr), "l"(gptr));
}

// ---------------------------------------------------------------------------
// setup_kernel: zero ys + split-K targets, reset barriers, copy h0 -> g_h[0]
// err_kernel:  err = ys - target (elementwise, after split-K O GEMM)
// ---------------------------------------------------------------------------
__global__ void setup_kernel(float* __restrict__ ys, int nys,
                             float* __restrict__ gw, int ngw,
                             const float* __restrict__ h0)
{
    int i = blockIdx.x * blockDim.x + threadIdx.x;
    if (i < 128) g_bars[i] = 0u;
    if (i < BH) g_h[i] = h0[i];
    for (int k = i; k < nys; k += gridDim.x * blockDim.x) ys[k] = 0.f;
    for (int k = i; k < ngw; k += gridDim.x * blockDim.x) gw[k] = 0.f;
}

__global__ void err_kernel(const float* __restrict__ ys,
                           const float* __restrict__ target)
{
    int i = blockIdx.x * blockDim.x + threadIdx.x;
    if (i < MROWS * Oo) g_err[i] = ys[i] - target[i];
}

// ---------------------------------------------------------------------------
// Forward scan: h_{t+1} = tanh(xin_t + h_t @ W_hh^T)
// (FROZEN at best-measured config: 4 groups x 32 slices, 256 thr; W_hh in
//  registers, warp w (0..7) = k-slice [128w,128w+128), lane jl = row.
//  Barrier: stores -> bar.sync -> atom.add.release.gpu + ld.acquire.gpu spin
//  — measured optimum; lane-parallel flag polling regressed 480us in R16.)
// ---------------------------------------------------------------------------
__global__ void __launch_bounds__(256, 1) scan_fwd(const float* __restrict__ Whh,
                                                   float* __restrict__ hf_out)
{
    __shared__ float hs[8 * Hh];          // 32KB staged h for this group's batches
    __shared__ float part[8 * 8 * 32];    // 8KB partials [kslice][b][j]

    int tid = threadIdx.x;
    int grp = blockIdx.x >> 5;            // batch group 0..3
    int sl  = blockIdx.x & 31;            // row slice 0..31
    int jbase = sl * 32;
    int bbase = grp * 8;

    int w  = tid >> 5;                    // k-slice == warp id (0..7)
    int jl = tid & 31;                    // row within slice (lane)
    int kbase = w * 128;

    // One-time: W[jbase+jl][kbase .. kbase+128) into 64 f32x2 registers
    unsigned long long wreg[64];
    {
        const float* wr = Whh + (size_t)(jbase + jl) * Hh + kbase;
        #pragma unroll
        for (int i = 0; i < 32; ++i) {
            F4U v; v.f = *(const float4*)&wr[i * 4];
            wreg[2 * i] = v.u[0]; wreg[2 * i + 1] = v.u[1];
        }
    }

    int eb = tid >> 5;                    // epilogue batch (0..7)
    int ej = tid & 31;                    // epilogue row within slice
    uint32_t hs_base = (uint32_t)__cvta_generic_to_shared(hs);
    unsigned* bar = &g_bars[grp * 32];

    for (int t = 0; t < Tt; ++t) {
        const float* hcur = g_h + (size_t)t * BH + (size_t)bbase * Hh;

        // Stage 8*1024 floats = 2048 float4 over 256 threads; 2 commit groups
        #pragma unroll
        for (int r = 0; r < 4; ++r) {
            int f = tid + (r << 8);
            cp16(hs_base + (f << 4), hcur + (f << 2));
        }
        asm volatile("cp.async.commit_group;\n");
        #pragma unroll
        for (int r = 4; r < 8; ++r) {
            int f = tid + (r << 8);
            cp16(hs_base + (f << 4), hcur + (f << 2));
        }
        asm volatile("cp.async.commit_group;\n");

        float accx = g_xin[(size_t)t * BH + (size_t)(bbase + eb) * Hh + jbase + ej];

        unsigned long long acc0[8], acc1[8];   // 2 chains per batch
        #pragma unroll
        for (int b = 0; b < 8; ++b) { acc0[b] = 0ull; acc1[b] = 0ull; }

        asm volatile("cp.async.wait_group 1;\n" ::: "memory");
        __syncthreads();
        #pragma unroll
        for (int b = 0; b < 4; ++b) {
            const float* hb = hs + b * Hh + kbase;
            #pragma unroll
            for (int i = 0; i < 32; ++i) {
                F4U hv; hv.f = *(const float4*)&hb[i * 4];   // warp-broadcast
                acc0[b] = ffma2_(hv.u[0], wreg[2 * i],     acc0[b]);
                acc1[b] = ffma2_(hv.u[1], wreg[2 * i + 1], acc1[b]);
            }
        }
        asm volatile("cp.async.wait_group 0;\n" ::: "memory");
        __syncthreads();
        #pragma unroll
        for (int b = 4; b < 8; ++b) {
            const float* hb = hs + b * Hh + kbase;
            #pragma unroll
            for (int i = 0; i < 32; ++i) {
                F4U hv; hv.f = *(const float4*)&hb[i * 4];
                acc0[b] = ffma2_(hv.u[0], wreg[2 * i],     acc0[b]);
                acc1[b] = ffma2_(hv.u[1], wreg[2 * i + 1], acc1[b]);
            }
        }

        // k-slice partials -> SMEM
        #pragma unroll
        for (int b = 0; b < 8; ++b) {
            U2F a, c; a.u = acc0[b]; c.u = acc1[b];
            part[w * 256 + b * 32 + jl] = (a.f.x + a.f.y) + (c.f.x + c.f.y);
        }
        __syncthreads();

        // Reduce 8 slices; thread (eb, ej)
        float s = accx;
        #pragma unroll
        for (int ww = 0; ww < 8; ++ww) s += part[ww * 256 + eb * 32 + ej];
        float hn = tanhf(s);
        __stcg(&g_h[(size_t)(t + 1) * BH + (size_t)(bbase + eb) * Hh + jbase + ej], hn);

        if (t == Tt - 1) {
            hf_out[(bbase + eb) * Hh + jbase + ej] = hn;
            break;
        }

        // Per-group barrier (32 CTAs): stores -> bar.sync -> release-add,
        // acquire-spin (single thread). No threadfence needed.
        __syncthreads();
        if (tid == 0) {
            unsigned prev;
            asm volatile("atom.add.release.gpu.u32 %0, [%1], %2;"
                         : "=r"(prev) : "l"(bar), "r"(1u) : "memory");
            unsigned tgt = (unsigned)(t + 1) * 32;
            unsigned v;
            do {
                asm volatile("ld.acquire.gpu.u32 %0, [%1];"
                             : "=r"(v) : "l"(bar) : "memory");
            } while (v < tgt);
        }
        __syncthreads();
    }
}

// ---------------------------------------------------------------------------
// Backward scan (elementwise, parallel over (b,j)):
//   a_t = c_t + diag(W_hh)[j] * (1 - h_all[t+1]^2) * a_{t+1}, in place in g_c
// ---------------------------------------------------------------------------
__global__ void scan_bwd(const float* __restrict__ Whh)
{
    int flat = blockIdx.x * blockDim.x + threadIdx.x;  // 0..BH-1
    int j = flat & (Hh - 1);
    float dw = Whh[(size_t)j * Hh + j];
    float a = g_c[(size_t)(Tt - 1) * BH + flat];
    for (int t = Tt - 2; t >= 0; --t) {
        float h   = g_h[(size_t)(t + 1) * BH + flat];
        float php = 1.f - h * h;
        a = g_c[(size_t)t * BH + flat] + dw * php * a;
        g_c[(size_t)t * BH + flat] = a;
    }
}

// ---------------------------------------------------------------------------
// GEMM core (engine frozen; fp32x2 inner, double-buffered, Bs rows 68 floats
// conflict-free, dup MOVs hidden under the FFMA2 floor). Device function so
// the three outer-product GEMMs can share ONE merged launch (gemm_outer3).
// SPLITK via bz (chunk length Kc) + ATOMIC epilogue into zeroed output.
// EPI: 0 plain store; 1 store + err=acc-Q0 into P1; 2 store acc*(1-Q0^2).
// ---------------------------------------------------------------------------
template<int TM, bool AKC, bool BKC, int EPI, bool ATOMIC>
__device__ __forceinline__ void gemm_core(const float* __restrict__ A, int sAm, int sAk,
                                          const float* __restrict__ B, int sBn, int sBk,
                                          int N, int Kc, float scale,
                                          float* __restrict__ P0, float* __restrict__ P1,
                                          const float* __restrict__ Q0,
                                          int bx, int by, int bz)
{
    constexpr int MI  = TM / 16;     // per-thread m extent (4 or 8)
    constexpr int NLA = TM / 64;     // A-loader iterations (1 or 2)
    __shared__ float As[2][16][TM + 4];
    __shared__ float Bs[2][16][68];
    int tid = threadIdx.x;
    int m0 = by * TM, n0 = bx * 64;
    int kbeg = bz * Kc, kend = kbeg + Kc;
    int ty = tid >> 4, tx = tid & 15;

    float4 aP[NLA], bP;
    auto loadA = [&](int k0) {
        #pragma unroll
        for (int it = 0; it < NLA; ++it) {
            int f = tid + (it << 8);
            if (AKC) { int r = f >> 2, kk = (f & 3) << 2;
                aP[it] = *(const float4*)&A[(size_t)(m0 + r) * sAm + k0 + kk]; }
            else { int kk = f / (TM / 4), r = (f % (TM / 4)) << 2;
                aP[it] = *(const float4*)&A[(size_t)(k0 + kk) * sAk + m0 + r]; }
        }
    };
    auto storeA = [&](int p) {
        #pragma unroll
        for (int it = 0; it < NLA; ++it) {
            int f = tid + (it << 8);
            if (AKC) { int r = f >> 2, kk = (f & 3) << 2;
                As[p][kk][r] = aP[it].x; As[p][kk+1][r] = aP[it].y;
                As[p][kk+2][r] = aP[it].z; As[p][kk+3][r] = aP[it].w; }
            else { int kk = f / (TM / 4), r = (f % (TM / 4)) << 2;
                *(float4*)&As[p][kk][r] = aP[it]; }
        }
    };
    auto loadB = [&](int k0) {
        if (BKC) { int r = tid >> 2, kk = (tid & 3) << 2;
            bP = *(const float4*)&B[(size_t)(n0 + r) * sBn + k0 + kk]; }
        else { int kk = tid >> 4, r = (tid & 15) << 2;
            bP = *(const float4*)&B[(size_t)(k0 + kk) * sBk + n0 + r]; }
    };
    auto storeB = [&](int p) {
        if (BKC) { int r = tid >> 2, kk = (tid & 3) << 2;
            Bs[p][kk][r] = bP.x; Bs[p][kk+1][r] = bP.y;
            Bs[p][kk+2][r] = bP.z; Bs[p][kk+3][r] = bP.w; }
        else { int kk = tid >> 4, r = (tid & 15) << 2;
            *(float4*)&Bs[p][kk][r] = bP; }
    };

    loadA(kbeg); loadB(kbeg);
    storeA(0);   storeB(0);
    __syncthreads();

    unsigned long long acc2[MI / 2][4];
    #pragma unroll
    for (int i = 0; i < MI / 2; ++i)
        #pragma unroll
        for (int j = 0; j < 4; ++j) acc2[i][j] = 0ull;

    int p = 0;
    for (int k0 = kbeg; k0 < kend; k0 += 16) {
        bool more = (k0 + 16) < kend;
        if (more) { loadA(k0 + 16); loadB(k0 + 16); }
        #pragma unroll
        for (int kk = 0; kk < 16; ++kk) {
            F4U bv; bv.f = *(float4*)&Bs[p][kk][tx << 2];
            unsigned long long d0 = dup2_(bv.s[0]), d1 = dup2_(bv.s[1]);
            unsigned long long d2 = dup2_(bv.s[2]), d3 = dup2_(bv.s[3]);
            #pragma unroll
            for (int q = 0; q < MI / 4; ++q) {
                F4U av; av.f = *(float4*)&As[p][kk][ty * MI + q * 4];
                acc2[2*q  ][0] = ffma2_(av.u[0], d0, acc2[2*q  ][0]);
                acc2[2*q+1][0] = ffma2_(av.u[1], d0, acc2[2*q+1][0]);
                acc2[2*q  ][1] = ffma2_(av.u[0], d1, acc2[2*q  ][1]);
                acc2[2*q+1][1] = ffma2_(av.u[1], d1, acc2[2*q+1][1]);
                acc2[2*q  ][2] = ffma2_(av.u[0], d2, acc2[2*q  ][2]);
                acc2[2*q+1][2] = ffma2_(av.u[1], d2, acc2[2*q+1][2]);
                acc2[2*q  ][3] = ffma2_(av.u[0], d3, acc2[2*q  ][3]);
                acc2[2*q+1][3] = ffma2_(av.u[1], d3, acc2[2*q+1][3]);
            }
        }
        if (more) { storeA(p ^ 1); storeB(p ^ 1); __syncthreads(); p ^= 1; }
    }

    // acc2[pr] holds m-offsets (2pr, 2pr+1) relative to ty*MI (pairs from the
    // float4 halves); epilogue enumerates m = m0 + ty*MI + pr*2 + h2.
    #pragma unroll
    for (int pr = 0; pr < MI / 2; ++pr) {
        #pragma unroll
        for (int h2 = 0; h2 < 2; ++h2) {
            int m = m0 + ty * MI + pr * 2 + h2;
            #pragma unroll
            for (int jx = 0; jx < 4; ++jx) {
                int n = n0 + (tx << 2) + jx;
                U2F uv; uv.u = acc2[pr][jx];
                float v = (h2 ? uv.f.y : uv.f.x) * scale;
                size_t idx = (size_t)m * N + n;
                if (ATOMIC) {
                    atomicAdd(&P0[idx], v);
                } else if (EPI == 0) {
                    P0[idx] = v;
                } else if (EPI == 1) {          // O -> ys, err = O - target
                    P0[idx] = v;
                    P1[idx] = v - Q0[idx];
                } else {                        // c = L * (1 - hnew^2)
                    float h = Q0[idx];
                    P0[idx] = v * (1.f - h * h);
                }
            }
        }
    }
}

template<int TM, bool AKC, bool BKC, int EPI, bool ATOMIC>
__global__ void __launch_bounds__(256) gemmT(const float* __restrict__ A, int sAm, int sAk,
                                             const float* __restrict__ B, int sBn, int sBk,
                                             int N, int Kc, float scale,
                                             float* __restrict__ P0, float* __restrict__ P1,
                                             const float* __restrict__ Q0)
{
    gemm_core<TM, AKC, BKC, EPI, ATOMIC>(A, sAm, sAk, B, sBn, sBk, N, Kc, scale,
                                         P0, P1, Q0,
                                         blockIdx.x, blockIdx.y, blockIdx.z);
}

// ---------------------------------------------------------------------------
// gemm_outer3: the three outer-product gradient GEMMs (identical
// instantiation gemm_core<128,false,false,0,true>) merged into ONE 1024-CTA
// launch — kills per-kernel wave-quantization tails (1.73/1.73/3.46 waves
// separately -> 6.9 waves merged) and two launch/drain gaps.
//   blocks [0,512):    g_whh  grid (16,8,4),  split 4,  scale 1e-5/B
//   blocks [512,768):  g_wout grid (16,1,16), split 16, scale 1/B
//   blocks [768,1024): g_wih  grid (4,8,8),   split 8,  scale 1e-3/B
// ---------------------------------------------------------------------------
__global__ void __launch_bounds__(256) gemm_outer3(
    const float* __restrict__ err,  const float* __restrict__ hnew,  float* __restrict__ gwout,
    const float* __restrict__ cc,   const float* __restrict__ x,     float* __restrict__ gwih,
    const float* __restrict__ hprev, float* __restrict__ gwhh)
{
    int b = blockIdx.x;
    if (b < 512) {
        int bx = b & 15, by = (b >> 4) & 7, bz = b >> 7;
        gemm_core<128, false, false, 0, true>(cc, 1, Hh, hprev, 1, Hh,
            Hh, MROWS / 4, 1e-5f / Bb, gwhh, nullptr, nullptr, bx, by, bz);
    } else if (b < 768) {
        int r = b - 512;
        int bx = r & 15, bz = r >> 4;
        gemm_core<128, false, false, 0, true>(err, 1, Oo, hnew, 1, Hh,
            Hh, MROWS / 16, 1.f / Bb, gwout, nullptr, nullptr, bx, 0, bz);
    } else {
        int r = b - 768;
        int bx = r & 3, by = (r >> 2) & 7, bz = r >> 5;
        gemm_core<128, false, false, 0, true>(cc, 1, Hh, x, 1, Ii,
            Ii, MROWS / 8, 1e-3f / Bb, gwih, nullptr, nullptr, bx, by, bz);
    }
}

// ---------------------------------------------------------------------------
// Launch sequence (graph-capturable: kernel launches only)
// ---------------------------------------------------------------------------
extern "C" void kernel_launch(void* const* d_in, const int* in_sizes, int n_in,
                              void* d_out, int out_size)
{
    const float* x      = (const float*)d_in[0];  // [T,B,I]
    const float* target = (const float*)d_in[1];  // [T,B,O]
    const float* h0     = (const float*)d_in[2];  // [B,H]
    const float* W_in   = (const float*)d_in[3];  // [H,I]
    const float* W_hh   = (const float*)d_in[4];  // [H,H]
    const float* W_out  = (const float*)d_in[5];  // [O,H]

    float* out   = (float*)d_out;
    float* ys    = out;                                   // [T*B, O]
    float* hf    = out + (size_t)MROWS * Oo;              // [B,H]
    float* gwout = hf + BH;                               // [O,H]
    float* gwih  = gwout + (size_t)Oo * Hh;               // [H,I]
    float* gwhh  = gwih + (size_t)Hh * Ii;                // [H,H]

    float *p_xin, *p_h, *p_err, *p_c;
    cudaGetSymbolAddress((void**)&p_xin, g_xin);
    cudaGetSymbolAddress((void**)&p_h,   g_h);
    cudaGetSymbolAddress((void**)&p_err, g_err);
    cudaGetSymbolAddress((void**)&p_c,   g_c);

    // 0. zero ys + split-K targets + barriers + h_all[0] (one kernel)
    // (kNumZero, NOT "NZERO": glibc <limits.h> defines NZERO=20 on the GPU host)
    const int kNumZero = Oo * Hh + Hh * Ii + Hh * Hh;   // gwout..gwhh contiguous
    setup_kernel<<<256, 256>>>(ys, MROWS * Oo, gwout, kNumZero, h0);

    // 1. Xin = X @ W_in^T            [4096,1024], K=256  (DOT)
    gemmT<128, true, true, 0, false><<<dim3(Hh / 64, MROWS / 128, 1), 256>>>(
        x, Ii, 1, W_in, Ii, 1, Hh, Ii, 1.f, p_xin, nullptr, nullptr);

    // 2. forward scan (persistent, 4 batch-groups x 32 slices, 256 thr)
    scan_fwd<<<128, 256>>>(W_hh, hf);

    // 3. O = Hnew @ W_out^T -> ys    [4096,128], K=1024, split 4 -> 512 CTAs
    gemmT<64, true, true, 0, true><<<dim3(Oo / 64, MROWS / 64, 4), 256>>>(
        p_h + BH, Hh, 1, W_out, Hh, 1, Oo, Hh / 4, 1.f, ys, nullptr, nullptr);

    // 4. err = ys - target (elementwise)
    err_kernel<<<(MROWS * Oo) / 256, 256>>>(ys, target);

    // 5. c = (err @ W_out) * (1 - hnew^2)                [4096,1024], K=128 (NN)
    gemmT<128, true, false, 2, false><<<dim3(Hh / 64, MROWS / 128, 1), 256>>>(
        p_err, Oo, 1, W_out, 1, Hh, Hh, Oo, 1.f, p_c, nullptr, p_h + BH);

    // 6. backward scan: c -> a (in place)
    scan_bwd<<<BH / 256, 256>>>(W_hh);

    // 7-9. merged outer-product gradients: g_whh + g_wout + g_wih, 1024 CTAs
    gemm_outer3<<<1024, 256>>>(p_err, p_h + BH, gwout,
                               p_c, x, gwih,
                               p_h, gwhh);
}